// round 16
// baseline (speedup 1.0000x reference)
#include <cuda_runtime.h>
#include <cuda_fp16.h>
#include <math.h>
#include <stdint.h>

// ---------------------------------------------------------------------------
// Problem constants (fixed shapes)
// ---------------------------------------------------------------------------
#define NWIN   4096
#define W      64
#define DIM    256
#define H      8
#define DH     32
#define HID    1024
#define M_ACT  2048
#define TOK    (M_ACT * W)        // 131072 active tokens
#define ROWS_ALL (NWIN * W)       // 262144 total rows
#define QKVC   (3 * DIM)          // 768

// ---------------------------------------------------------------------------
// Scratch (device globals; allocation inside kernel_launch is forbidden)
// ---------------------------------------------------------------------------
__device__ __half g_xh  [(size_t)ROWS_ALL * DIM];  // LN1 out, half (GEMM A)
__device__ __half g_qkv [(size_t)TOK * QKVC];
__device__ __half g_attn[(size_t)TOK * DIM];
__device__ float  g_h   [(size_t)TOK * DIM];       // residual stream, fp32
__device__ __half g_h2  [(size_t)TOK * DIM];
__device__ __half g_hid [(size_t)TOK * HID];
__device__ int    g_rowmap[TOK];

// transposed + fp16-rounded weights, [N, K] K-major, concatenated
#define WOFF_QKV  0
#define WOFF_PROJ (DIM * QKVC)
#define WOFF_FC1  (WOFF_PROJ + DIM * DIM)
#define WOFF_FC2  (WOFF_FC1 + DIM * HID)
#define WTOTAL    (WOFF_FC2 + HID * DIM)
__device__ __half g_wh[WTOTAL];

// ---------------------------------------------------------------------------
// helpers
// ---------------------------------------------------------------------------
__device__ __forceinline__ uint32_t h2u(half2 h) {
    return *reinterpret_cast<uint32_t*>(&h);
}

// ---------------------------------------------------------------------------
// Weight transpose + fp16 round: dst[n*K + k] = (half)src[k*N + n]
// ---------------------------------------------------------------------------
__global__ void wtrans_kernel(const float* __restrict__ src,
                              __half* __restrict__ dst, int K, int N)
{
    int i = blockIdx.x * blockDim.x + threadIdx.x;
    if (i < K * N) {
        int n = i / K, k = i - n * K;
        dst[i] = __float2half_rn(src[(size_t)k * N + n]);
    }
}

// ---------------------------------------------------------------------------
// Row map
// ---------------------------------------------------------------------------
__global__ void rowmap_kernel(const int* __restrict__ index) {
    int t = blockIdx.x * blockDim.x + threadIdx.x;
    if (t < TOK) g_rowmap[t] = index[t >> 6] * W + (t & (W - 1));
}

// ---------------------------------------------------------------------------
// LayerNorm (one warp per row). Writes optional fp32 stream + half stream.
// ---------------------------------------------------------------------------
template<bool WRITE_F32>
__global__ __launch_bounds__(256)
void ln_kernel(const float* __restrict__ in, float* __restrict__ outf,
               __half* __restrict__ outh,
               const float* __restrict__ gam, const float* __restrict__ bet,
               int nrows)
{
    int warp = threadIdx.x >> 5;
    int lane = threadIdx.x & 31;
    int row  = blockIdx.x * 8 + warp;
    if (row >= nrows) return;

    const float* p = in + (size_t)row * DIM;
    float4 v0 = *(const float4*)(p + lane * 4);
    float4 v1 = *(const float4*)(p + 128 + lane * 4);

    float s = v0.x + v0.y + v0.z + v0.w + v1.x + v1.y + v1.z + v1.w;
    #pragma unroll
    for (int o = 16; o > 0; o >>= 1) s += __shfl_xor_sync(0xffffffffu, s, o);
    float mu = s * (1.0f / 256.0f);

    float d0 = v0.x - mu, d1 = v0.y - mu, d2 = v0.z - mu, d3 = v0.w - mu;
    float d4 = v1.x - mu, d5 = v1.y - mu, d6 = v1.z - mu, d7 = v1.w - mu;
    float vs = d0*d0 + d1*d1 + d2*d2 + d3*d3 + d4*d4 + d5*d5 + d6*d6 + d7*d7;
    #pragma unroll
    for (int o = 16; o > 0; o >>= 1) vs += __shfl_xor_sync(0xffffffffu, vs, o);
    float inv = rsqrtf(vs * (1.0f / 256.0f) + 1e-5f);

    float4 g0 = *(const float4*)(gam + lane * 4);
    float4 g1 = *(const float4*)(gam + 128 + lane * 4);
    float4 b0 = *(const float4*)(bet + lane * 4);
    float4 b1 = *(const float4*)(bet + 128 + lane * 4);

    float4 o0, o1;
    o0.x = d0 * inv * g0.x + b0.x;  o0.y = d1 * inv * g0.y + b0.y;
    o0.z = d2 * inv * g0.z + b0.z;  o0.w = d3 * inv * g0.w + b0.w;
    o1.x = d4 * inv * g1.x + b1.x;  o1.y = d5 * inv * g1.y + b1.y;
    o1.z = d6 * inv * g1.z + b1.z;  o1.w = d7 * inv * g1.w + b1.w;

    if (WRITE_F32) {
        float* q = outf + (size_t)row * DIM;
        *(float4*)(q + lane * 4) = o0;
        *(float4*)(q + 128 + lane * 4) = o1;
    }
    __half* qh = outh + (size_t)row * DIM;
    *(half2*)(qh + lane * 4)           = __floats2half2_rn(o0.x, o0.y);
    *(half2*)(qh + lane * 4 + 2)       = __floats2half2_rn(o0.z, o0.w);
    *(half2*)(qh + 128 + lane * 4)     = __floats2half2_rn(o1.x, o1.y);
    *(half2*)(qh + 128 + lane * 4 + 2) = __floats2half2_rn(o1.z, o1.w);
}

// ---------------------------------------------------------------------------
// Common mma/ldmatrix helpers
// ---------------------------------------------------------------------------
__device__ __forceinline__ void cp_async16s(uint32_t smem, const void* gmem) {
    asm volatile("cp.async.cg.shared.global [%0], [%1], 16;\n" :: "r"(smem), "l"(gmem));
}
__device__ __forceinline__ void cp_commit() { asm volatile("cp.async.commit_group;\n"); }
template<int N> __device__ __forceinline__ void cp_wait() {
    asm volatile("cp.async.wait_group %0;\n" :: "n"(N));
}

__device__ __forceinline__ void ldmx4(uint32_t* r, uint32_t addr) {
    asm volatile("ldmatrix.sync.aligned.m8n8.x4.shared.b16 {%0,%1,%2,%3}, [%4];"
                 : "=r"(r[0]), "=r"(r[1]), "=r"(r[2]), "=r"(r[3]) : "r"(addr));
}

__device__ __forceinline__ void mma_f16(float* c, const uint32_t* a, const uint32_t* b) {
    asm volatile(
        "mma.sync.aligned.m16n8k16.row.col.f32.f16.f16.f32 "
        "{%0,%1,%2,%3},{%4,%5,%6,%7},{%8,%9},{%0,%1,%2,%3};\n"
        : "+f"(c[0]), "+f"(c[1]), "+f"(c[2]), "+f"(c[3])
        : "r"(a[0]), "r"(a[1]), "r"(a[2]), "r"(a[3]), "r"(b[0]), "r"(b[1]));
}

// ---------------------------------------------------------------------------
// fp16 tensor-core GEMM: C[M,N] = A[M,K] @ Bt[N,K]^T + bias
// CTA tile 128x256, 512 threads (16 warps, 4M x 4N), warp tile 32x64,
// BK=32 halves, 3-stage cp.async pipeline, single __syncthreads per iter.
// ---------------------------------------------------------------------------
#define NSTG 3
#define BKH 32
#define ASTRH 40                          // halves per smem row (80B, conflict-free)
#define ASTG (128 * ASTRH * 2)            // 10240 B per A stage
#define BSTG (256 * ASTRH * 2)            // 20480 B per B stage
#define SMEM_G (NSTG * (ASTG + BSTG))     // 92160 B

template<int EPI, bool OUTH>
__global__ __launch_bounds__(512)
void gemm_h(const __half* __restrict__ A, const int* __restrict__ rowmapA,
            const __half* __restrict__ Bt, const float* __restrict__ bias,
            void* __restrict__ Cv, const int* __restrict__ rowmapC,
            const float* __restrict__ Res, const int* __restrict__ rowmapRes,
            int Ncols, int K)
{
    extern __shared__ __align__(16) char dyn[];
    const uint32_t sbase = (uint32_t)__cvta_generic_to_shared(dyn);

    const int tid = threadIdx.x;
    const int rowBase = blockIdx.y * 128;
    const int colBase = blockIdx.x * 256;

    // A loader: all 512 threads, 1 chunk each: row = tid>>2 (0..127), chunk = tid&3
    const int ar = tid >> 2;
    const int ac = tid & 3;
    const int gra = rowBase + ar;
    const size_t arow = rowmapA ? (size_t)rowmapA[gra] : (size_t)gra;
    const __half* Ag = A + arow * (size_t)K + ac * 8;
    const uint32_t aOff = (uint32_t)(ar * 80 + ac * 16);

    // B loader: all 512 threads, 2 chunks each: row = tid>>1 (0..255), chunks (tid&1)*2, +1
    const int br = tid >> 1;
    const int bc = (tid & 1) * 2;
    const __half* Bg = Bt + (size_t)(colBase + br) * K + bc * 8;
    const uint32_t bOff = (uint32_t)(br * 80 + bc * 16);

    const int warp  = tid >> 5;
    const int lane  = tid & 31;
    const int warpM = warp >> 2;     // 0..3, 32 rows
    const int warpN = warp & 3;      // 0..3, 64 cols
    const int grp   = lane >> 2;
    const int tig   = lane & 3;

    float acc[2][8][4];
    #pragma unroll
    for (int mt = 0; mt < 2; mt++)
        #pragma unroll
        for (int nt = 0; nt < 8; nt++)
            #pragma unroll
            for (int j = 0; j < 4; j++) acc[mt][nt][j] = 0.0f;

    const int KT = K / BKH;

    auto issue = [&](int kt) {
        const int s = kt % NSTG;
        const uint32_t aB = sbase + s * ASTG;
        const uint32_t bB = sbase + NSTG * ASTG + s * BSTG;
        cp_async16s(aB + aOff, Ag + kt * BKH);
        cp_async16s(bB + bOff,      Bg + kt * BKH);
        cp_async16s(bB + bOff + 16, Bg + kt * BKH + 8);
        cp_commit();
    };

    issue(0);
    issue(1);

    const uint32_t aLdRow = (uint32_t)(warpM * 32 + (lane & 15));
    const uint32_t aLdCol = (uint32_t)((lane >> 4) * 8);
    const uint32_t bLdRow0 = (uint32_t)(warpN * 64 + (lane & 7) + (lane >> 4) * 8);
    const uint32_t bLdCol = (uint32_t)(((lane >> 3) & 1) * 8);

    for (int kt = 0; kt < KT; kt++) {
        if (kt < KT - 1) cp_wait<1>(); else cp_wait<0>();
        __syncthreads();
        if (kt + 2 < KT) issue(kt + 2);

        const int s = kt % NSTG;
        const uint32_t aB = sbase + s * ASTG;
        const uint32_t bB = sbase + NSTG * ASTG + s * BSTG;

        #pragma unroll
        for (int ks = 0; ks < 2; ks++) {
            const uint32_t kb = (uint32_t)(ks * 16);

            uint32_t afr[2][4];
            #pragma unroll
            for (int mt = 0; mt < 2; mt++)
                ldmx4(afr[mt], aB + ((aLdRow + mt * 16) * ASTRH + kb + aLdCol) * 2);

            uint32_t bfr[8][2];
            #pragma unroll
            for (int np = 0; np < 4; np++) {
                uint32_t t[4];
                ldmx4(t, bB + ((bLdRow0 + np * 16) * ASTRH + kb + bLdCol) * 2);
                bfr[2 * np][0]     = t[0];
                bfr[2 * np][1]     = t[1];
                bfr[2 * np + 1][0] = t[2];
                bfr[2 * np + 1][1] = t[3];
            }
            #pragma unroll
            for (int mt = 0; mt < 2; mt++)
                #pragma unroll
                for (int nt = 0; nt < 8; nt++)
                    mma_f16(acc[mt][nt], afr[mt], bfr[nt]);
        }
    }

    // ---------------- Epilogue ----------------
    #pragma unroll
    for (int mt = 0; mt < 2; mt++) {
        #pragma unroll
        for (int hf = 0; hf < 2; hf++) {
            const int gr = rowBase + warpM * 32 + mt * 16 + grp + hf * 8;
            const size_t crow = rowmapC ? (size_t)rowmapC[gr] : (size_t)gr;
            const float* Rp = nullptr;
            if (EPI == 2) {
                const size_t rrow = rowmapRes ? (size_t)rowmapRes[gr] : (size_t)gr;
                Rp = Res + rrow * (size_t)Ncols;
            }
            #pragma unroll
            for (int nt = 0; nt < 8; nt++) {
                const int col = colBase + warpN * 64 + nt * 8 + 2 * tig;
                float v0 = acc[mt][nt][hf * 2 + 0] + __ldg(bias + col);
                float v1 = acc[mt][nt][hf * 2 + 1] + __ldg(bias + col + 1);
                if (EPI == 1) {
                    v0 = 0.5f * v0 * (1.0f + erff(v0 * 0.70710678118654752f));
                    v1 = 0.5f * v1 * (1.0f + erff(v1 * 0.70710678118654752f));
                }
                if (EPI == 2) { v0 += Rp[col]; v1 += Rp[col + 1]; }
                if (OUTH) {
                    __half* Cp = (__half*)Cv + crow * (size_t)Ncols;
                    *(half2*)(Cp + col) = __floats2half2_rn(v0, v1);
                } else {
                    float* Cp = (float*)Cv + crow * (size_t)Ncols;
                    *(float2*)(Cp + col) = make_float2(v0, v1);
                }
            }
        }
    }
}

// ---------------------------------------------------------------------------
// Tensor-core attention (unchanged from R15 — passing).
// CTA = 256 threads = 8 warps = 4 window-heads (2 warps each).
// ---------------------------------------------------------------------------
#define AQS 2560          // 64*40 halves per wh (Q or K)
#define AVS 2304          // 32*72 halves per wh (Vt)
#define SMEM_ATTN ((4 * (2 * AQS + AVS)) * 2)   // 59392 bytes

__global__ __launch_bounds__(256)
void attn_mma_kernel(const __half* __restrict__ qkv, __half* __restrict__ attn_out)
{
    extern __shared__ __align__(16) char dynb[];
    __half* sm = (__half*)dynb;

    const int tid = threadIdx.x;

    for (int i = tid; i < 4096; i += 256) {
        const int widx = i >> 10;
        const int row  = (i >> 4) & 63;
        const int dp   = (i & 15) * 2;
        const int whg  = blockIdx.x * 4 + widx;
        const int m = whg >> 3, h = whg & 7;
        const __half* rp = qkv + ((size_t)m * W + row) * QKVC + h * (3 * DH);
        half2 q2 = *(const half2*)(rp + dp);
        half2 k2 = *(const half2*)(rp + DH + dp);
        half2 v2 = *(const half2*)(rp + 2 * DH + dp);
        *(half2*)(sm + widx * AQS + row * 40 + dp)            = q2;
        *(half2*)(sm + 4 * AQS + widx * AQS + row * 40 + dp)  = k2;
        __half* vt = sm + 8 * AQS + widx * AVS;
        vt[(dp)     * 72 + row] = __low2half(v2);
        vt[(dp + 1) * 72 + row] = __high2half(v2);
    }
    __syncthreads();

    const int warp = tid >> 5;
    const int lane = tid & 31;
    const int widx = warp >> 1;
    const int p    = warp & 1;
    const int whg  = blockIdx.x * 4 + widx;
    const int m = whg >> 3, h = whg & 7;

    const uint32_t sQ = (uint32_t)__cvta_generic_to_shared(sm + widx * AQS);
    const uint32_t sK = (uint32_t)__cvta_generic_to_shared(sm + 4 * AQS + widx * AQS);
    const uint32_t sV = (uint32_t)__cvta_generic_to_shared(sm + 8 * AQS + widx * AVS);

    const int grp = lane >> 2;
    const int tig = lane & 3;
    const uint32_t aRow = (uint32_t)(p * 32 + (lane & 15));
    const uint32_t aCol = (uint32_t)((lane >> 4) * 8);
    const uint32_t bRow = (uint32_t)((lane & 7) + (lane >> 4) * 8);
    const uint32_t bCol = (uint32_t)(((lane >> 3) & 1) * 8);

    uint32_t qf[2][2][4];
    #pragma unroll
    for (int mt = 0; mt < 2; mt++)
        #pragma unroll
        for (int ks = 0; ks < 2; ks++)
            ldmx4(qf[mt][ks], sQ + ((aRow + mt * 16) * 40 + ks * 16 + aCol) * 2);

    float sacc[2][8][4];
    #pragma unroll
    for (int mt = 0; mt < 2; mt++)
        #pragma unroll
        for (int nt = 0; nt < 8; nt++)
            #pragma unroll
            for (int j = 0; j < 4; j++) sacc[mt][nt][j] = 0.0f;

    #pragma unroll
    for (int ks = 0; ks < 2; ks++) {
        uint32_t bf[8][2];
        #pragma unroll
        for (int np = 0; np < 4; np++) {
            uint32_t t[4];
            ldmx4(t, sK + ((bRow + np * 16) * 40 + ks * 16 + bCol) * 2);
            bf[2 * np][0] = t[0]; bf[2 * np][1] = t[1];
            bf[2 * np + 1][0] = t[2]; bf[2 * np + 1][1] = t[3];
        }
        #pragma unroll
        for (int mt = 0; mt < 2; mt++)
            #pragma unroll
            for (int nt = 0; nt < 8; nt++)
                mma_f16(sacc[mt][nt], qf[mt][ks], bf[nt]);
    }

    const float scale = 0.17677669529663687f;
    #pragma unroll
    for (int mt = 0; mt < 2; mt++) {
        #pragma unroll
        for (int rh = 0; rh < 2; rh++) {
            float mx = -1e30f;
            #pragma unroll
            for (int nt = 0; nt < 8; nt++)
                mx = fmaxf(mx, fmaxf(sacc[mt][nt][rh * 2], sacc[mt][nt][rh * 2 + 1]));
            mx = fmaxf(mx, __shfl_xor_sync(0xffffffffu, mx, 1));
            mx = fmaxf(mx, __shfl_xor_sync(0xffffffffu, mx, 2));
            float sum = 0.0f;
            #pragma unroll
            for (int nt = 0; nt < 8; nt++) {
                float e0 = __expf((sacc[mt][nt][rh * 2]     - mx) * scale);
                float e1 = __expf((sacc[mt][nt][rh * 2 + 1] - mx) * scale);
                sacc[mt][nt][rh * 2] = e0; sacc[mt][nt][rh * 2 + 1] = e1;
                sum += e0 + e1;
            }
            sum += __shfl_xor_sync(0xffffffffu, sum, 1);
            sum += __shfl_xor_sync(0xffffffffu, sum, 2);
            const float inv = 1.0f / sum;
            #pragma unroll
            for (int nt = 0; nt < 8; nt++) {
                sacc[mt][nt][rh * 2]     *= inv;
                sacc[mt][nt][rh * 2 + 1] *= inv;
            }
        }
    }

    uint32_t pa[2][4][4];
    #pragma unroll
    for (int mt = 0; mt < 2; mt++)
        #pragma unroll
        for (int kt = 0; kt < 4; kt++) {
            pa[mt][kt][0] = h2u(__floats2half2_rn(sacc[mt][2*kt][0],   sacc[mt][2*kt][1]));
            pa[mt][kt][1] = h2u(__floats2half2_rn(sacc[mt][2*kt][2],   sacc[mt][2*kt][3]));
            pa[mt][kt][2] = h2u(__floats2half2_rn(sacc[mt][2*kt+1][0], sacc[mt][2*kt+1][1]));
            pa[mt][kt][3] = h2u(__floats2half2_rn(sacc[mt][2*kt+1][2], sacc[mt][2*kt+1][3]));
        }

    float oacc[2][4][4];
    #pragma unroll
    for (int mt = 0; mt < 2; mt++)
        #pragma unroll
        for (int nt = 0; nt < 4; nt++)
            #pragma unroll
            for (int j = 0; j < 4; j++) oacc[mt][nt][j] = 0.0f;

    #pragma unroll
    for (int kt = 0; kt < 4; kt++) {
        uint32_t vf[4][2];
        #pragma unroll
        for (int np = 0; np < 2; np++) {
            uint32_t t[4];
            ldmx4(t, sV + ((bRow + np * 16) * 72 + kt * 16 + bCol) * 2);
            vf[2 * np][0] = t[0]; vf[2 * np][1] = t[1];
            vf[2 * np + 1][0] = t[2]; vf[2 * np + 1][1] = t[3];
        }
        #pragma unroll
        for (int mt = 0; mt < 2; mt++)
            #pragma unroll
            for (int nt = 0; nt < 4; nt++)
                mma_f16(oacc[mt][nt], pa[mt][kt], vf[nt]);
    }

    __half* ob = attn_out + (size_t)m * W * DIM + h * DH;
    #pragma unroll
    for (int mt = 0; mt < 2; mt++) {
        const int row0 = p * 32 + mt * 16 + grp;
        #pragma unroll
        for (int nt = 0; nt < 4; nt++) {
            const int col = nt * 8 + 2 * tig;
            *(half2*)(ob + (size_t)row0 * DIM + col) =
                __floats2half2_rn(oacc[mt][nt][0], oacc[mt][nt][1]);
            *(half2*)(ob + (size_t)(row0 + 8) * DIM + col) =
                __floats2half2_rn(oacc[mt][nt][2], oacc[mt][nt][3]);
        }
    }
}

// ---------------------------------------------------------------------------
// Launch
// ---------------------------------------------------------------------------
extern "C" void kernel_launch(void* const* d_in, const int* in_sizes, int n_in,
                              void* d_out, int out_size)
{
    int k = 0;
    const float* x      = (const float*)d_in[k++];
    const int*   index  = (const int*)  d_in[k++];
    if (n_in >= 15) k++;  // skip scalar M slot if present
    const float* n1g    = (const float*)d_in[k++];
    const float* n1b    = (const float*)d_in[k++];
    const float* qkv_w  = (const float*)d_in[k++];
    const float* qkv_b  = (const float*)d_in[k++];
    const float* proj_w = (const float*)d_in[k++];
    const float* proj_b = (const float*)d_in[k++];
    const float* n2g    = (const float*)d_in[k++];
    const float* n2b    = (const float*)d_in[k++];
    const float* fc1_w  = (const float*)d_in[k++];
    const float* fc1_b  = (const float*)d_in[k++];
    const float* fc2_w  = (const float*)d_in[k++];
    const float* fc2_b  = (const float*)d_in[k++];

    float* X = (float*)d_out;

    __half *p_xh, *p_qkv, *p_attn, *p_h2, *p_hid, *p_wh;
    float *p_h;
    int *p_rowmap;
    cudaGetSymbolAddress((void**)&p_xh,     g_xh);
    cudaGetSymbolAddress((void**)&p_qkv,    g_qkv);
    cudaGetSymbolAddress((void**)&p_attn,   g_attn);
    cudaGetSymbolAddress((void**)&p_h,      g_h);
    cudaGetSymbolAddress((void**)&p_h2,     g_h2);
    cudaGetSymbolAddress((void**)&p_hid,    g_hid);
    cudaGetSymbolAddress((void**)&p_wh,     g_wh);
    cudaGetSymbolAddress((void**)&p_rowmap, g_rowmap);

    cudaFuncSetAttribute(gemm_h<0, true>,  cudaFuncAttributeMaxDynamicSharedMemorySize, SMEM_G);
    cudaFuncSetAttribute(gemm_h<1, true>,  cudaFuncAttributeMaxDynamicSharedMemorySize, SMEM_G);
    cudaFuncSetAttribute(gemm_h<2, false>, cudaFuncAttributeMaxDynamicSharedMemorySize, SMEM_G);
    cudaFuncSetAttribute(attn_mma_kernel,  cudaFuncAttributeMaxDynamicSharedMemorySize, SMEM_ATTN);

    // 0) transpose + fp16-round weights -> [N,K] K-major
    wtrans_kernel<<<(DIM*QKVC + 255)/256, 256>>>(qkv_w,  p_wh + WOFF_QKV,  DIM, QKVC);
    wtrans_kernel<<<(DIM*DIM  + 255)/256, 256>>>(proj_w, p_wh + WOFF_PROJ, DIM, DIM);
    wtrans_kernel<<<(DIM*HID  + 255)/256, 256>>>(fc1_w,  p_wh + WOFF_FC1,  DIM, HID);
    wtrans_kernel<<<(HID*DIM  + 255)/256, 256>>>(fc2_w,  p_wh + WOFF_FC2,  HID, DIM);

    // 1) LayerNorm1: exact fp32 -> d_out, half copy -> g_xh
    ln_kernel<true><<<ROWS_ALL / 8, 256>>>(x, X, p_xh, n1g, n1b, ROWS_ALL);

    // 2) Row map
    rowmap_kernel<<<TOK / 256, 256>>>(index);

    // 3) QKV: gather(g_xh) @ qkv_w + b -> g_qkv (half)  [131072 x 768]
    gemm_h<0, true><<<dim3(QKVC/256, TOK/128), 512, SMEM_G>>>(
        p_xh, p_rowmap, p_wh + WOFF_QKV, qkv_b, p_qkv, nullptr, nullptr, nullptr, QKVC, DIM);

    // 4) Attention (tensor-core) -> g_attn (half)
    attn_mma_kernel<<<M_ACT * H / 4, 256, SMEM_ATTN>>>(p_qkv, p_attn);

    // 5) Proj + shortcut(gathered fp32 X) -> g_h (fp32)
    gemm_h<2, false><<<dim3(DIM/256, TOK/128), 512, SMEM_G>>>(
        p_attn, nullptr, p_wh + WOFF_PROJ, proj_b, p_h, nullptr, X, p_rowmap, DIM, DIM);

    // 6) LayerNorm2: g_h -> g_h2 (half only)
    ln_kernel<false><<<TOK / 8, 256>>>(p_h, nullptr, p_h2, n2g, n2b, TOK);

    // 7) FC1 + GELU -> g_hid (half)  [131072 x 1024]
    gemm_h<1, true><<<dim3(HID/256, TOK/128), 512, SMEM_G>>>(
        p_h2, nullptr, p_wh + WOFF_FC1, fc1_b, p_hid, nullptr, nullptr, nullptr, HID, DIM);

    // 8) FC2 + residual(g_h fp32), scatter fp32 rows into d_out
    gemm_h<2, false><<<dim3(DIM/256, TOK/128), 512, SMEM_G>>>(
        p_hid, nullptr, p_wh + WOFF_FC2, fc2_b, X, p_rowmap, p_h, nullptr, DIM, HID);

    (void)in_sizes; (void)out_size;
}

// round 17
// speedup vs baseline: 1.0478x; 1.0478x over previous
#include <cuda_runtime.h>
#include <cuda_fp16.h>
#include <math.h>
#include <stdint.h>

// ---------------------------------------------------------------------------
// Problem constants (fixed shapes)
// ---------------------------------------------------------------------------
#define NWIN   4096
#define W      64
#define DIM    256
#define H      8
#define DH     32
#define HID    1024
#define M_ACT  2048
#define TOK    (M_ACT * W)        // 131072 active tokens
#define ROWS_ALL (NWIN * W)       // 262144 total rows
#define QKVC   (3 * DIM)          // 768

// ---------------------------------------------------------------------------
// Scratch (device globals; allocation inside kernel_launch is forbidden)
// ---------------------------------------------------------------------------
__device__ __half g_xh  [(size_t)ROWS_ALL * DIM];  // LN1 out, half (GEMM A)
__device__ __half g_qkv [(size_t)TOK * QKVC];
__device__ __half g_attn[(size_t)TOK * DIM];
__device__ float  g_h   [(size_t)TOK * DIM];       // residual stream, fp32
__device__ __half g_h2  [(size_t)TOK * DIM];
__device__ __half g_hid [(size_t)TOK * HID];
__device__ int    g_rowmap[TOK];

// transposed + fp16-rounded weights, [N, K] K-major, concatenated
#define WOFF_QKV  0
#define WOFF_PROJ (DIM * QKVC)
#define WOFF_FC1  (WOFF_PROJ + DIM * DIM)
#define WOFF_FC2  (WOFF_FC1 + DIM * HID)
#define WTOTAL    (WOFF_FC2 + HID * DIM)
__device__ __half g_wh[WTOTAL];

// ---------------------------------------------------------------------------
// helpers
// ---------------------------------------------------------------------------
__device__ __forceinline__ uint32_t h2u(half2 h) {
    return *reinterpret_cast<uint32_t*>(&h);
}

__global__ void wtrans_kernel(const float* __restrict__ src,
                              __half* __restrict__ dst, int K, int N)
{
    int i = blockIdx.x * blockDim.x + threadIdx.x;
    if (i < K * N) {
        int n = i / K, k = i - n * K;
        dst[i] = __float2half_rn(src[(size_t)k * N + n]);
    }
}

__global__ void rowmap_kernel(const int* __restrict__ index) {
    int t = blockIdx.x * blockDim.x + threadIdx.x;
    if (t < TOK) g_rowmap[t] = index[t >> 6] * W + (t & (W - 1));
}

// ---------------------------------------------------------------------------
// LayerNorm1 (one warp per row). Writes fp32 stream + half stream.
// ---------------------------------------------------------------------------
__global__ __launch_bounds__(256)
void ln_kernel(const float* __restrict__ in, float* __restrict__ outf,
               __half* __restrict__ outh,
               const float* __restrict__ gam, const float* __restrict__ bet,
               int nrows)
{
    int warp = threadIdx.x >> 5;
    int lane = threadIdx.x & 31;
    int row  = blockIdx.x * 8 + warp;
    if (row >= nrows) return;

    const float* p = in + (size_t)row * DIM;
    float4 v0 = *(const float4*)(p + lane * 4);
    float4 v1 = *(const float4*)(p + 128 + lane * 4);

    float s = v0.x + v0.y + v0.z + v0.w + v1.x + v1.y + v1.z + v1.w;
    #pragma unroll
    for (int o = 16; o > 0; o >>= 1) s += __shfl_xor_sync(0xffffffffu, s, o);
    float mu = s * (1.0f / 256.0f);

    float d0 = v0.x - mu, d1 = v0.y - mu, d2 = v0.z - mu, d3 = v0.w - mu;
    float d4 = v1.x - mu, d5 = v1.y - mu, d6 = v1.z - mu, d7 = v1.w - mu;
    float vs = d0*d0 + d1*d1 + d2*d2 + d3*d3 + d4*d4 + d5*d5 + d6*d6 + d7*d7;
    #pragma unroll
    for (int o = 16; o > 0; o >>= 1) vs += __shfl_xor_sync(0xffffffffu, vs, o);
    float inv = rsqrtf(vs * (1.0f / 256.0f) + 1e-5f);

    float4 g0 = *(const float4*)(gam + lane * 4);
    float4 g1 = *(const float4*)(gam + 128 + lane * 4);
    float4 b0 = *(const float4*)(bet + lane * 4);
    float4 b1 = *(const float4*)(bet + 128 + lane * 4);

    float4 o0, o1;
    o0.x = d0 * inv * g0.x + b0.x;  o0.y = d1 * inv * g0.y + b0.y;
    o0.z = d2 * inv * g0.z + b0.z;  o0.w = d3 * inv * g0.w + b0.w;
    o1.x = d4 * inv * g1.x + b1.x;  o1.y = d5 * inv * g1.y + b1.y;
    o1.z = d6 * inv * g1.z + b1.z;  o1.w = d7 * inv * g1.w + b1.w;

    float* q = outf + (size_t)row * DIM;
    *(float4*)(q + lane * 4) = o0;
    *(float4*)(q + 128 + lane * 4) = o1;

    __half* qh = outh + (size_t)row * DIM;
    *(half2*)(qh + lane * 4)           = __floats2half2_rn(o0.x, o0.y);
    *(half2*)(qh + lane * 4 + 2)       = __floats2half2_rn(o0.z, o0.w);
    *(half2*)(qh + 128 + lane * 4)     = __floats2half2_rn(o1.x, o1.y);
    *(half2*)(qh + 128 + lane * 4 + 2) = __floats2half2_rn(o1.z, o1.w);
}

// ---------------------------------------------------------------------------
// Common mma/ldmatrix helpers
// ---------------------------------------------------------------------------
__device__ __forceinline__ void cp_async16s(uint32_t smem, const void* gmem) {
    asm volatile("cp.async.cg.shared.global [%0], [%1], 16;\n" :: "r"(smem), "l"(gmem));
}
__device__ __forceinline__ void cp_commit() { asm volatile("cp.async.commit_group;\n"); }
template<int N> __device__ __forceinline__ void cp_wait() {
    asm volatile("cp.async.wait_group %0;\n" :: "n"(N));
}

__device__ __forceinline__ void ldmx4(uint32_t* r, uint32_t addr) {
    asm volatile("ldmatrix.sync.aligned.m8n8.x4.shared.b16 {%0,%1,%2,%3}, [%4];"
                 : "=r"(r[0]), "=r"(r[1]), "=r"(r[2]), "=r"(r[3]) : "r"(addr));
}

__device__ __forceinline__ void mma_f16(float* c, const uint32_t* a, const uint32_t* b) {
    asm volatile(
        "mma.sync.aligned.m16n8k16.row.col.f32.f16.f16.f32 "
        "{%0,%1,%2,%3},{%4,%5,%6,%7},{%8,%9},{%0,%1,%2,%3};\n"
        : "+f"(c[0]), "+f"(c[1]), "+f"(c[2]), "+f"(c[3])
        : "r"(a[0]), "r"(a[1]), "r"(a[2]), "r"(a[3]), "r"(b[0]), "r"(b[1]));
}

// ---------------------------------------------------------------------------
// fp16 tensor-core GEMM (qkv / fc1 / fc2): C = A @ Bt^T + bias
// CTA tile 128x128, 256 threads, 8 warps (4x2), warp tile 32x64.
// NSTG=4 stages, pair-blocked mainloop: ONE sync + ONE wait per 2 k-tiles.
// ---------------------------------------------------------------------------
#define NSTG 4
#define BKH 32
#define ASTRH 40
#define STAGEB (128 * ASTRH * 2)          // 10240 B per matrix per stage
#define SMEM_H (2 * NSTG * STAGEB)        // 81920 B

template<int EPI, bool OUTH>
__global__ __launch_bounds__(256)
void gemm_h(const __half* __restrict__ A, const int* __restrict__ rowmapA,
            const __half* __restrict__ Bt, const float* __restrict__ bias,
            void* __restrict__ Cv, const int* __restrict__ rowmapC,
            const float* __restrict__ Res, const int* __restrict__ rowmapRes,
            int Ncols, int K)
{
    extern __shared__ __align__(16) char dyn[];
    const uint32_t sbase = (uint32_t)__cvta_generic_to_shared(dyn);

    const int tid = threadIdx.x;
    const int rowBase = blockIdx.y * 128;
    const int colBase = blockIdx.x * 128;

    const int r  = tid >> 1;
    const int c0 = (tid & 1) * 2;
    const int gra = rowBase + r;
    const size_t arow = rowmapA ? (size_t)rowmapA[gra] : (size_t)gra;
    const __half* Ag = A + arow * (size_t)K;
    const __half* Bg = Bt + (size_t)(colBase + r) * K;
    const uint32_t sArow = (uint32_t)(r * 80);

    const int warp  = tid >> 5;
    const int lane  = tid & 31;
    const int warpM = warp >> 1;
    const int warpN = warp & 1;
    const int grp   = lane >> 2;
    const int tig   = lane & 3;

    float acc[2][8][4];
    #pragma unroll
    for (int mt = 0; mt < 2; mt++)
        #pragma unroll
        for (int nt = 0; nt < 8; nt++)
            #pragma unroll
            for (int j = 0; j < 4; j++) acc[mt][nt][j] = 0.0f;

    const int KT = K / BKH;

    auto issue = [&](int kt) {
        const int s = kt % NSTG;
        const uint32_t aB = sbase + s * STAGEB;
        const uint32_t bB = sbase + NSTG * STAGEB + s * STAGEB;
        const __half* ag = Ag + kt * BKH;
        const __half* bg = Bg + kt * BKH;
        cp_async16s(aB + sArow + c0 * 16,       ag + c0 * 8);
        cp_async16s(aB + sArow + (c0 + 1) * 16, ag + (c0 + 1) * 8);
        cp_async16s(bB + sArow + c0 * 16,       bg + c0 * 8);
        cp_async16s(bB + sArow + (c0 + 1) * 16, bg + (c0 + 1) * 8);
        cp_commit();
    };

    const uint32_t aLdRow = (uint32_t)(warpM * 32 + (lane & 15));
    const uint32_t aLdCol = (uint32_t)((lane >> 4) * 8);
    const uint32_t bLdRow0 = (uint32_t)(warpN * 64 + (lane & 7) + (lane >> 4) * 8);
    const uint32_t bLdCol = (uint32_t)(((lane >> 3) & 1) * 8);

    auto compute_stage = [&](int kt) {
        const int s = kt % NSTG;
        const uint32_t aB = sbase + s * STAGEB;
        const uint32_t bB = sbase + NSTG * STAGEB + s * STAGEB;
        #pragma unroll
        for (int ks = 0; ks < 2; ks++) {
            const uint32_t kb = (uint32_t)(ks * 16);
            uint32_t afr[2][4];
            #pragma unroll
            for (int mt = 0; mt < 2; mt++)
                ldmx4(afr[mt], aB + ((aLdRow + mt * 16) * ASTRH + kb + aLdCol) * 2);
            uint32_t bfr[8][2];
            #pragma unroll
            for (int np = 0; np < 4; np++) {
                uint32_t t[4];
                ldmx4(t, bB + ((bLdRow0 + np * 16) * ASTRH + kb + bLdCol) * 2);
                bfr[2 * np][0]     = t[0];
                bfr[2 * np][1]     = t[1];
                bfr[2 * np + 1][0] = t[2];
                bfr[2 * np + 1][1] = t[3];
            }
            #pragma unroll
            for (int mt = 0; mt < 2; mt++)
                #pragma unroll
                for (int nt = 0; nt < 8; nt++)
                    mma_f16(acc[mt][nt], afr[mt], bfr[nt]);
        }
    };

    issue(0);
    issue(1);

    // pair-blocked mainloop: KT is even for all uses (8 / 8 / 32)
    for (int j = 0; j < KT; j += 2) {
        cp_wait<0>();
        __syncthreads();
        if (j + 2 < KT) { issue(j + 2); issue(j + 3); }
        compute_stage(j);
        compute_stage(j + 1);
    }

    // ---------------- Epilogue ----------------
    #pragma unroll
    for (int mt = 0; mt < 2; mt++) {
        #pragma unroll
        for (int hf = 0; hf < 2; hf++) {
            const int gr = rowBase + warpM * 32 + mt * 16 + grp + hf * 8;
            const size_t crow = rowmapC ? (size_t)rowmapC[gr] : (size_t)gr;
            const float* Rp = nullptr;
            if (EPI == 2) {
                const size_t rrow = rowmapRes ? (size_t)rowmapRes[gr] : (size_t)gr;
                Rp = Res + rrow * (size_t)Ncols;
            }
            #pragma unroll
            for (int nt = 0; nt < 8; nt++) {
                const int col = colBase + warpN * 64 + nt * 8 + 2 * tig;
                float v0 = acc[mt][nt][hf * 2 + 0] + __ldg(bias + col);
                float v1 = acc[mt][nt][hf * 2 + 1] + __ldg(bias + col + 1);
                if (EPI == 1) {
                    v0 = 0.5f * v0 * (1.0f + erff(v0 * 0.70710678118654752f));
                    v1 = 0.5f * v1 * (1.0f + erff(v1 * 0.70710678118654752f));
                }
                if (EPI == 2) { v0 += Rp[col]; v1 += Rp[col + 1]; }
                if (OUTH) {
                    __half* Cp = (__half*)Cv + crow * (size_t)Ncols;
                    *(half2*)(Cp + col) = __floats2half2_rn(v0, v1);
                } else {
                    float* Cp = (float*)Cv + crow * (size_t)Ncols;
                    *(float2*)(Cp + col) = make_float2(v0, v1);
                }
            }
        }
    }
}

// ---------------------------------------------------------------------------
// Fused proj GEMM + residual + LayerNorm2.
// CTA tile 128x256 (full DIM rows), 512 threads (16 warps 4x4), K=256, NSTG=3.
// Writes h = attn@W + b + shortcut (fp32, g_h) AND LN2(h) (half, g_h2).
// ---------------------------------------------------------------------------
#define PSTG 3
#define PASTG (128 * ASTRH * 2)           // 10240
#define PBSTG (256 * ASTRH * 2)           // 20480
#define SMEM_P (PSTG * (PASTG + PBSTG))   // 92160

__global__ __launch_bounds__(512)
void gemm_proj_ln(const __half* __restrict__ A, const __half* __restrict__ Bt,
                  const float* __restrict__ bias,
                  const float* __restrict__ Res, const int* __restrict__ rowmapRes,
                  float* __restrict__ Hout, __half* __restrict__ H2out,
                  const float* __restrict__ gam, const float* __restrict__ bet)
{
    extern __shared__ __align__(16) char dyn[];
    const uint32_t sbase = (uint32_t)__cvta_generic_to_shared(dyn);

    const int tid = threadIdx.x;
    const int rowBase = blockIdx.x * 128;

    // A loader: row = tid>>2 (0..127), chunk = tid&3 (8 halves each)
    const int ar = tid >> 2;
    const int ac = tid & 3;
    const __half* Ag = A + (size_t)(rowBase + ar) * DIM + ac * 8;
    const uint32_t aOff = (uint32_t)(ar * 80 + ac * 16);

    // B loader: row = tid>>1 (0..255), chunks (tid&1)*2, +1
    const int br = tid >> 1;
    const int bc = (tid & 1) * 2;
    const __half* Bg = Bt + (size_t)br * DIM + bc * 8;
    const uint32_t bOff = (uint32_t)(br * 80 + bc * 16);

    const int warp  = tid >> 5;
    const int lane  = tid & 31;
    const int warpM = warp >> 2;     // 0..3
    const int warpN = warp & 3;      // 0..3
    const int grp   = lane >> 2;
    const int tig   = lane & 3;

    float acc[2][8][4];
    #pragma unroll
    for (int mt = 0; mt < 2; mt++)
        #pragma unroll
        for (int nt = 0; nt < 8; nt++)
            #pragma unroll
            for (int j = 0; j < 4; j++) acc[mt][nt][j] = 0.0f;

    const int KT = DIM / BKH;   // 8

    auto issue = [&](int kt) {
        const int s = kt % PSTG;
        const uint32_t aB = sbase + s * PASTG;
        const uint32_t bB = sbase + PSTG * PASTG + s * PBSTG;
        cp_async16s(aB + aOff, Ag + kt * BKH);
        cp_async16s(bB + bOff,      Bg + kt * BKH);
        cp_async16s(bB + bOff + 16, Bg + kt * BKH + 8);
        cp_commit();
    };

    issue(0);
    issue(1);

    const uint32_t aLdRow = (uint32_t)(warpM * 32 + (lane & 15));
    const uint32_t aLdCol = (uint32_t)((lane >> 4) * 8);
    const uint32_t bLdRow0 = (uint32_t)(warpN * 64 + (lane & 7) + (lane >> 4) * 8);
    const uint32_t bLdCol = (uint32_t)(((lane >> 3) & 1) * 8);

    for (int kt = 0; kt < KT; kt++) {
        if (kt < KT - 1) cp_wait<1>(); else cp_wait<0>();
        __syncthreads();
        if (kt + 2 < KT) issue(kt + 2);

        const int s = kt % PSTG;
        const uint32_t aB = sbase + s * PASTG;
        const uint32_t bB = sbase + PSTG * PASTG + s * PBSTG;

        #pragma unroll
        for (int ks = 0; ks < 2; ks++) {
            const uint32_t kb = (uint32_t)(ks * 16);
            uint32_t afr[2][4];
            #pragma unroll
            for (int mt = 0; mt < 2; mt++)
                ldmx4(afr[mt], aB + ((aLdRow + mt * 16) * ASTRH + kb + aLdCol) * 2);
            uint32_t bfr[8][2];
            #pragma unroll
            for (int np = 0; np < 4; np++) {
                uint32_t t[4];
                ldmx4(t, bB + ((bLdRow0 + np * 16) * ASTRH + kb + bLdCol) * 2);
                bfr[2 * np][0]     = t[0];
                bfr[2 * np][1]     = t[1];
                bfr[2 * np + 1][0] = t[2];
                bfr[2 * np + 1][1] = t[3];
            }
            #pragma unroll
            for (int mt = 0; mt < 2; mt++)
                #pragma unroll
                for (int nt = 0; nt < 8; nt++)
                    mma_f16(acc[mt][nt], afr[mt], bfr[nt]);
        }
    }

    // ---- Epilogue phase 1: v = acc + bias + residual (in place), h write,
    //      per-(row, warp) partial sums reduced within quads ----
    float s1v[2][2], s2v[2][2];
    #pragma unroll
    for (int mt = 0; mt < 2; mt++) {
        #pragma unroll
        for (int hf = 0; hf < 2; hf++) {
            const int gr = rowBase + warpM * 32 + mt * 16 + hf * 8 + grp;
            const size_t rrow = (size_t)rowmapRes[gr];
            const float* Rp = Res + rrow * DIM;
            float* Hp = Hout + (size_t)gr * DIM;
            float s1 = 0.0f, s2 = 0.0f;
            #pragma unroll
            for (int nt = 0; nt < 8; nt++) {
                const int col = warpN * 64 + nt * 8 + 2 * tig;
                float v0 = acc[mt][nt][hf * 2 + 0] + __ldg(bias + col) + Rp[col];
                float v1 = acc[mt][nt][hf * 2 + 1] + __ldg(bias + col + 1) + Rp[col + 1];
                acc[mt][nt][hf * 2 + 0] = v0;
                acc[mt][nt][hf * 2 + 1] = v1;
                s1 += v0 + v1;
                s2 += v0 * v0 + v1 * v1;
                *(float2*)(Hp + col) = make_float2(v0, v1);
            }
            s1 += __shfl_xor_sync(0xffffffffu, s1, 1);
            s1 += __shfl_xor_sync(0xffffffffu, s1, 2);
            s2 += __shfl_xor_sync(0xffffffffu, s2, 1);
            s2 += __shfl_xor_sync(0xffffffffu, s2, 2);
            s1v[mt][hf] = s1;
            s2v[mt][hf] = s2;
        }
    }

    // protect pipeline smem from still-running mainloop warps, then stage partials
    __syncthreads();
    float* S1 = (float*)dyn;          // [128][4]
    float* S2 = S1 + 512;             // [128][4]
    #pragma unroll
    for (int mt = 0; mt < 2; mt++)
        #pragma unroll
        for (int hf = 0; hf < 2; hf++) {
            const int rloc = warpM * 32 + mt * 16 + hf * 8 + grp;
            if (tig == 0) {
                S1[rloc * 4 + warpN] = s1v[mt][hf];
                S2[rloc * 4 + warpN] = s2v[mt][hf];
            }
        }
    __syncthreads();

    // ---- Epilogue phase 2: LN transform, half write ----
    #pragma unroll
    for (int mt = 0; mt < 2; mt++) {
        #pragma unroll
        for (int hf = 0; hf < 2; hf++) {
            const int rloc = warpM * 32 + mt * 16 + hf * 8 + grp;
            const int gr = rowBase + rloc;
            float sum = S1[rloc * 4 + 0] + S1[rloc * 4 + 1] + S1[rloc * 4 + 2] + S1[rloc * 4 + 3];
            float sq  = S2[rloc * 4 + 0] + S2[rloc * 4 + 1] + S2[rloc * 4 + 2] + S2[rloc * 4 + 3];
            float mu  = sum * (1.0f / 256.0f);
            float inv = rsqrtf(sq * (1.0f / 256.0f) - mu * mu + 1e-5f);
            __half* Hp2 = H2out + (size_t)gr * DIM;
            #pragma unroll
            for (int nt = 0; nt < 8; nt++) {
                const int col = warpN * 64 + nt * 8 + 2 * tig;
                float t0 = (acc[mt][nt][hf * 2 + 0] - mu) * inv * __ldg(gam + col) + __ldg(bet + col);
                float t1 = (acc[mt][nt][hf * 2 + 1] - mu) * inv * __ldg(gam + col + 1) + __ldg(bet + col + 1);
                *(half2*)(Hp2 + col) = __floats2half2_rn(t0, t1);
            }
        }
    }
}

// ---------------------------------------------------------------------------
// Tensor-core attention (unchanged — passing at R15).
// ---------------------------------------------------------------------------
#define AQS 2560
#define AVS 2304
#define SMEM_ATTN ((4 * (2 * AQS + AVS)) * 2)   // 59392 bytes

__global__ __launch_bounds__(256)
void attn_mma_kernel(const __half* __restrict__ qkv, __half* __restrict__ attn_out)
{
    extern __shared__ __align__(16) char dynb[];
    __half* sm = (__half*)dynb;

    const int tid = threadIdx.x;

    for (int i = tid; i < 4096; i += 256) {
        const int widx = i >> 10;
        const int row  = (i >> 4) & 63;
        const int dp   = (i & 15) * 2;
        const int whg  = blockIdx.x * 4 + widx;
        const int m = whg >> 3, h = whg & 7;
        const __half* rp = qkv + ((size_t)m * W + row) * QKVC + h * (3 * DH);
        half2 q2 = *(const half2*)(rp + dp);
        half2 k2 = *(const half2*)(rp + DH + dp);
        half2 v2 = *(const half2*)(rp + 2 * DH + dp);
        *(half2*)(sm + widx * AQS + row * 40 + dp)            = q2;
        *(half2*)(sm + 4 * AQS + widx * AQS + row * 40 + dp)  = k2;
        __half* vt = sm + 8 * AQS + widx * AVS;
        vt[(dp)     * 72 + row] = __low2half(v2);
        vt[(dp + 1) * 72 + row] = __high2half(v2);
    }
    __syncthreads();

    const int warp = tid >> 5;
    const int lane = tid & 31;
    const int widx = warp >> 1;
    const int p    = warp & 1;
    const int whg  = blockIdx.x * 4 + widx;
    const int m = whg >> 3, h = whg & 7;

    const uint32_t sQ = (uint32_t)__cvta_generic_to_shared(sm + widx * AQS);
    const uint32_t sK = (uint32_t)__cvta_generic_to_shared(sm + 4 * AQS + widx * AQS);
    const uint32_t sV = (uint32_t)__cvta_generic_to_shared(sm + 8 * AQS + widx * AVS);

    const int grp = lane >> 2;
    const int tig = lane & 3;
    const uint32_t aRow = (uint32_t)(p * 32 + (lane & 15));
    const uint32_t aCol = (uint32_t)((lane >> 4) * 8);
    const uint32_t bRow = (uint32_t)((lane & 7) + (lane >> 4) * 8);
    const uint32_t bCol = (uint32_t)(((lane >> 3) & 1) * 8);

    uint32_t qf[2][2][4];
    #pragma unroll
    for (int mt = 0; mt < 2; mt++)
        #pragma unroll
        for (int ks = 0; ks < 2; ks++)
            ldmx4(qf[mt][ks], sQ + ((aRow + mt * 16) * 40 + ks * 16 + aCol) * 2);

    float sacc[2][8][4];
    #pragma unroll
    for (int mt = 0; mt < 2; mt++)
        #pragma unroll
        for (int nt = 0; nt < 8; nt++)
            #pragma unroll
            for (int j = 0; j < 4; j++) sacc[mt][nt][j] = 0.0f;

    #pragma unroll
    for (int ks = 0; ks < 2; ks++) {
        uint32_t bf[8][2];
        #pragma unroll
        for (int np = 0; np < 4; np++) {
            uint32_t t[4];
            ldmx4(t, sK + ((bRow + np * 16) * 40 + ks * 16 + bCol) * 2);
            bf[2 * np][0] = t[0]; bf[2 * np][1] = t[1];
            bf[2 * np + 1][0] = t[2]; bf[2 * np + 1][1] = t[3];
        }
        #pragma unroll
        for (int mt = 0; mt < 2; mt++)
            #pragma unroll
            for (int nt = 0; nt < 8; nt++)
                mma_f16(sacc[mt][nt], qf[mt][ks], bf[nt]);
    }

    const float scale = 0.17677669529663687f;
    #pragma unroll
    for (int mt = 0; mt < 2; mt++) {
        #pragma unroll
        for (int rh = 0; rh < 2; rh++) {
            float mx = -1e30f;
            #pragma unroll
            for (int nt = 0; nt < 8; nt++)
                mx = fmaxf(mx, fmaxf(sacc[mt][nt][rh * 2], sacc[mt][nt][rh * 2 + 1]));
            mx = fmaxf(mx, __shfl_xor_sync(0xffffffffu, mx, 1));
            mx = fmaxf(mx, __shfl_xor_sync(0xffffffffu, mx, 2));
            float sum = 0.0f;
            #pragma unroll
            for (int nt = 0; nt < 8; nt++) {
                float e0 = __expf((sacc[mt][nt][rh * 2]     - mx) * scale);
                float e1 = __expf((sacc[mt][nt][rh * 2 + 1] - mx) * scale);
                sacc[mt][nt][rh * 2] = e0; sacc[mt][nt][rh * 2 + 1] = e1;
                sum += e0 + e1;
            }
            sum += __shfl_xor_sync(0xffffffffu, sum, 1);
            sum += __shfl_xor_sync(0xffffffffu, sum, 2);
            const float inv = 1.0f / sum;
            #pragma unroll
            for (int nt = 0; nt < 8; nt++) {
                sacc[mt][nt][rh * 2]     *= inv;
                sacc[mt][nt][rh * 2 + 1] *= inv;
            }
        }
    }

    uint32_t pa[2][4][4];
    #pragma unroll
    for (int mt = 0; mt < 2; mt++)
        #pragma unroll
        for (int kt = 0; kt < 4; kt++) {
            pa[mt][kt][0] = h2u(__floats2half2_rn(sacc[mt][2*kt][0],   sacc[mt][2*kt][1]));
            pa[mt][kt][1] = h2u(__floats2half2_rn(sacc[mt][2*kt][2],   sacc[mt][2*kt][3]));
            pa[mt][kt][2] = h2u(__floats2half2_rn(sacc[mt][2*kt+1][0], sacc[mt][2*kt+1][1]));
            pa[mt][kt][3] = h2u(__floats2half2_rn(sacc[mt][2*kt+1][2], sacc[mt][2*kt+1][3]));
        }

    float oacc[2][4][4];
    #pragma unroll
    for (int mt = 0; mt < 2; mt++)
        #pragma unroll
        for (int nt = 0; nt < 4; nt++)
            #pragma unroll
            for (int j = 0; j < 4; j++) oacc[mt][nt][j] = 0.0f;

    #pragma unroll
    for (int kt = 0; kt < 4; kt++) {
        uint32_t vf[4][2];
        #pragma unroll
        for (int np = 0; np < 2; np++) {
            uint32_t t[4];
            ldmx4(t, sV + ((bRow + np * 16) * 72 + kt * 16 + bCol) * 2);
            vf[2 * np][0] = t[0]; vf[2 * np][1] = t[1];
            vf[2 * np + 1][0] = t[2]; vf[2 * np + 1][1] = t[3];
        }
        #pragma unroll
        for (int mt = 0; mt < 2; mt++)
            #pragma unroll
            for (int nt = 0; nt < 4; nt++)
                mma_f16(oacc[mt][nt], pa[mt][kt], vf[nt]);
    }

    __half* ob = attn_out + (size_t)m * W * DIM + h * DH;
    #pragma unroll
    for (int mt = 0; mt < 2; mt++) {
        const int row0 = p * 32 + mt * 16 + grp;
        #pragma unroll
        for (int nt = 0; nt < 4; nt++) {
            const int col = nt * 8 + 2 * tig;
            *(half2*)(ob + (size_t)row0 * DIM + col) =
                __floats2half2_rn(oacc[mt][nt][0], oacc[mt][nt][1]);
            *(half2*)(ob + (size_t)(row0 + 8) * DIM + col) =
                __floats2half2_rn(oacc[mt][nt][2], oacc[mt][nt][3]);
        }
    }
}

// ---------------------------------------------------------------------------
// Launch
// ---------------------------------------------------------------------------
extern "C" void kernel_launch(void* const* d_in, const int* in_sizes, int n_in,
                              void* d_out, int out_size)
{
    int k = 0;
    const float* x      = (const float*)d_in[k++];
    const int*   index  = (const int*)  d_in[k++];
    if (n_in >= 15) k++;  // skip scalar M slot if present
    const float* n1g    = (const float*)d_in[k++];
    const float* n1b    = (const float*)d_in[k++];
    const float* qkv_w  = (const float*)d_in[k++];
    const float* qkv_b  = (const float*)d_in[k++];
    const float* proj_w = (const float*)d_in[k++];
    const float* proj_b = (const float*)d_in[k++];
    const float* n2g    = (const float*)d_in[k++];
    const float* n2b    = (const float*)d_in[k++];
    const float* fc1_w  = (const float*)d_in[k++];
    const float* fc1_b  = (const float*)d_in[k++];
    const float* fc2_w  = (const float*)d_in[k++];
    const float* fc2_b  = (const float*)d_in[k++];

    float* X = (float*)d_out;

    __half *p_xh, *p_qkv, *p_attn, *p_h2, *p_hid, *p_wh;
    float *p_h;
    int *p_rowmap;
    cudaGetSymbolAddress((void**)&p_xh,     g_xh);
    cudaGetSymbolAddress((void**)&p_qkv,    g_qkv);
    cudaGetSymbolAddress((void**)&p_attn,   g_attn);
    cudaGetSymbolAddress((void**)&p_h,      g_h);
    cudaGetSymbolAddress((void**)&p_h2,     g_h2);
    cudaGetSymbolAddress((void**)&p_hid,    g_hid);
    cudaGetSymbolAddress((void**)&p_wh,     g_wh);
    cudaGetSymbolAddress((void**)&p_rowmap, g_rowmap);

    cudaFuncSetAttribute(gemm_h<0, true>,  cudaFuncAttributeMaxDynamicSharedMemorySize, SMEM_H);
    cudaFuncSetAttribute(gemm_h<1, true>,  cudaFuncAttributeMaxDynamicSharedMemorySize, SMEM_H);
    cudaFuncSetAttribute(gemm_h<2, false>, cudaFuncAttributeMaxDynamicSharedMemorySize, SMEM_H);
    cudaFuncSetAttribute(gemm_proj_ln,     cudaFuncAttributeMaxDynamicSharedMemorySize, SMEM_P);
    cudaFuncSetAttribute(attn_mma_kernel,  cudaFuncAttributeMaxDynamicSharedMemorySize, SMEM_ATTN);

    // 0) transpose + fp16-round weights -> [N,K] K-major
    wtrans_kernel<<<(DIM*QKVC + 255)/256, 256>>>(qkv_w,  p_wh + WOFF_QKV,  DIM, QKVC);
    wtrans_kernel<<<(DIM*DIM  + 255)/256, 256>>>(proj_w, p_wh + WOFF_PROJ, DIM, DIM);
    wtrans_kernel<<<(DIM*HID  + 255)/256, 256>>>(fc1_w,  p_wh + WOFF_FC1,  DIM, HID);
    wtrans_kernel<<<(HID*DIM  + 255)/256, 256>>>(fc2_w,  p_wh + WOFF_FC2,  HID, DIM);

    // 1) LayerNorm1: exact fp32 -> d_out, half copy -> g_xh
    ln_kernel<<<ROWS_ALL / 8, 256>>>(x, X, p_xh, n1g, n1b, ROWS_ALL);

    // 2) Row map
    rowmap_kernel<<<TOK / 256, 256>>>(index);

    // 3) QKV: gather(g_xh) @ qkv_w + b -> g_qkv (half)  [131072 x 768]
    gemm_h<0, true><<<dim3(QKVC/128, TOK/128), 256, SMEM_H>>>(
        p_xh, p_rowmap, p_wh + WOFF_QKV, qkv_b, p_qkv, nullptr, nullptr, nullptr, QKVC, DIM);

    // 4) Attention (tensor-core) -> g_attn (half)
    attn_mma_kernel<<<M_ACT * H / 4, 256, SMEM_ATTN>>>(p_qkv, p_attn);

    // 5+6) Fused: proj GEMM + shortcut + LayerNorm2 -> g_h (fp32), g_h2 (half)
    gemm_proj_ln<<<TOK / 128, 512, SMEM_P>>>(
        p_attn, p_wh + WOFF_PROJ, proj_b, X, p_rowmap, p_h, p_h2, n2g, n2b);

    // 7) FC1 + GELU -> g_hid (half)  [131072 x 1024]
    gemm_h<1, true><<<dim3(HID/128, TOK/128), 256, SMEM_H>>>(
        p_h2, nullptr, p_wh + WOFF_FC1, fc1_b, p_hid, nullptr, nullptr, nullptr, HID, DIM);

    // 8) FC2 + residual(g_h fp32), scatter fp32 rows into d_out
    gemm_h<2, false><<<dim3(DIM/128, TOK/128), 256, SMEM_H>>>(
        p_hid, nullptr, p_wh + WOFF_FC2, fc2_b, X, p_rowmap, p_h, nullptr, DIM, HID);

    (void)in_sizes; (void)out_size;
}